// round 13
// baseline (speedup 1.0000x reference)
#include <cuda_runtime.h>
#include <cuda_fp16.h>
#include <stdint.h>

#define B_   16
#define LK_  2048
#define LQ_  256
#define DIM_ 512
#define H_   8
#define DK_  64
#define M_   (B_ * LQ_)     // 4096

// ---------------- helpers ----------------
__device__ __forceinline__ uint32_t pack_h2(float x, float y) {
    __half2 h = __float22half2_rn(make_float2(x, y));
    return *(uint32_t*)&h;
}
__device__ __forceinline__ void pack_split_h(float x, float y,
                                             uint32_t& hi, uint32_t& lo) {
    __half2 h = __float22half2_rn(make_float2(x, y));
    float2 hf = __half22float2(h);
    __half2 l = __float22half2_rn(make_float2(x - hf.x, y - hf.y));
    hi = *(uint32_t*)&h;
    lo = *(uint32_t*)&l;
}
__device__ __forceinline__ float ex2f(float x) {
    float r; asm("ex2.approx.f32 %0, %1;" : "=f"(r) : "f"(x)); return r;
}
__device__ __forceinline__ void ldsm4(uint32_t* r, uint32_t addr) {
    asm volatile("ldmatrix.sync.aligned.m8n8.x4.shared.b16 {%0,%1,%2,%3}, [%4];"
        : "=r"(r[0]), "=r"(r[1]), "=r"(r[2]), "=r"(r[3]) : "r"(addr));
}
__device__ __forceinline__ void ldsm4t(uint32_t* r, uint32_t addr) {
    asm volatile("ldmatrix.sync.aligned.m8n8.x4.trans.shared.b16 {%0,%1,%2,%3}, [%4];"
        : "=r"(r[0]), "=r"(r[1]), "=r"(r[2]), "=r"(r[3]) : "r"(addr));
}
__device__ __forceinline__ void mma16816(float* c, const uint32_t* a,
                                         uint32_t b0, uint32_t b1) {
    asm volatile("mma.sync.aligned.m16n8k16.row.col.f32.f16.f16.f32 "
        "{%0,%1,%2,%3}, {%4,%5,%6,%7}, {%8,%9}, {%0,%1,%2,%3};"
        : "+f"(c[0]), "+f"(c[1]), "+f"(c[2]), "+f"(c[3])
        : "r"(a[0]), "r"(a[1]), "r"(a[2]), "r"(a[3]), "r"(b0), "r"(b1));
}
__device__ __forceinline__ void cp16(uint32_t dst, const void* src) {
    asm volatile("cp.async.cg.shared.global [%0], [%1], 16;" :: "r"(dst), "l"(src));
}

// ---------------- scratch (__device__ globals) ----------------
__device__ float  g_q  [M_ * DIM_];
__device__ __half g_gh [M_ * DIM_];
__device__ __half g_xh [M_ * DIM_];
__device__ __half g_wqh[DIM_ * DIM_];
__device__ __half g_woh[DIM_ * DIM_], g_wol[DIM_ * DIM_];

// ---------------------------------------------------------------------------
// Prep: G -> fp16; Wq -> fp16 (single); Wo -> fp16 hi/lo
// ---------------------------------------------------------------------------
#define NG (M_ * DIM_ / 2)
#define NW (DIM_ * DIM_ / 2)

__global__ void prep_kernel(const float* __restrict__ G,
                            const float* __restrict__ Wq,
                            const float* __restrict__ Wo) {
    int i = blockIdx.x * blockDim.x + threadIdx.x;
    if (i < NG) {
        float2 v = ((const float2*)G)[i];
        ((uint32_t*)g_gh)[i] = pack_h2(v.x, v.y);
    } else if (i < NG + NW) {
        int j = i - NG;
        float2 v = ((const float2*)Wq)[j];
        ((uint32_t*)g_wqh)[j] = pack_h2(v.x, v.y);
    } else if (i < NG + 2 * NW) {
        int j = i - NG - NW;
        float2 v = ((const float2*)Wo)[j];
        uint32_t h, l;
        pack_split_h(v.x, v.y, h, l);
        ((uint32_t*)g_woh)[j] = h; ((uint32_t*)g_wol)[j] = l;
    }
}

// ---------------------------------------------------------------------------
// GEMM 1-term (Q projection) — exact R11 structure.
// ---------------------------------------------------------------------------
#define G1_STAGE 12288
#define G1_WH    8192
#define GEMM1_SMEM (3 * G1_STAGE)   // 36 KB

__global__ __launch_bounds__(256, 2)
void gemm1_kernel(const __half* __restrict__ Ah,
                  const __half* __restrict__ Wh,
                  const float* __restrict__ bias,
                  float* __restrict__ C) {
    extern __shared__ char sm[];
    const uint32_t sb = (uint32_t)__cvta_generic_to_shared(sm);
    const int tid = threadIdx.x, wid = tid >> 5, lane = tid & 31;
    const int g = lane >> 2, t = lane & 3;
    const int wm = wid & 3, wn = wid >> 2;
    const int n0 = blockIdx.x * 64, m0 = blockIdx.y * 128;

    auto issue = [&](int kb, int st) {
        uint32_t base = sb + (uint32_t)st * G1_STAGE;
        #pragma unroll
        for (int i = 0; i < 2; ++i) {
            int lin = tid + i * 256;
            int row = lin >> 2, c = lin & 3;
            uint32_t off = (uint32_t)(row * 64 + c * 16);
            off ^= (off >> 3) & 0x30;
            cp16(base + off, Ah + (size_t)(m0 + row) * DIM_ + kb * 32 + c * 8);
        }
        {
            int row = tid >> 3, c = tid & 7;
            uint32_t off = (uint32_t)(row * 128 + c * 16);
            off ^= (off >> 3) & 0x70;
            cp16(base + G1_WH + off, Wh + (size_t)(kb * 32 + row) * DIM_ + n0 + c * 8);
        }
        asm volatile("cp.async.commit_group;");
    };

    float acc[2][4][4];
    #pragma unroll
    for (int i = 0; i < 2; ++i)
        #pragma unroll
        for (int j = 0; j < 4; ++j)
            #pragma unroll
            for (int r = 0; r < 4; ++r) acc[i][j][r] = 0.f;

    const uint32_t aColByte = (uint32_t)((lane >> 4) * 16);
    const uint32_t xr    = (uint32_t)(lane & 7) << 4;
    const uint32_t wRowB = (uint32_t)((lane & 15) * 128);
    const uint32_t wD    = (uint32_t)((lane >> 4) * 16);
    const uint32_t wCol  = (uint32_t)(wn * 64);

    issue(0, 0);
    issue(1, 1);

    for (int kb = 0; kb < 16; ++kb) {
        asm volatile("cp.async.wait_group 1;");
        __syncthreads();
        if (kb + 2 < 16) issue(kb + 2, (kb + 2) % 3);

        uint32_t base = sb + (uint32_t)(kb % 3) * G1_STAGE;
        #pragma unroll
        for (int s = 0; s < 2; ++s) {
            uint32_t af[2][4];
            #pragma unroll
            for (int mf = 0; mf < 2; ++mf) {
                uint32_t off = (uint32_t)((wm * 32 + mf * 16 + (lane & 15)) * 64)
                             + (uint32_t)(s * 32) + aColByte;
                off ^= (off >> 3) & 0x30;
                ldsm4(af[mf], base + off);
            }
            #pragma unroll
            for (int nq = 0; nq < 2; ++nq) {
                uint32_t wo = (uint32_t)(s * 16 * 128) + wRowB +
                              ((wCol + (uint32_t)(nq * 32) + wD) ^ xr);
                uint32_t bh[4];
                ldsm4t(bh, base + G1_WH + wo);
                #pragma unroll
                for (int mf = 0; mf < 2; ++mf) {
                    mma16816(acc[mf][2 * nq],     af[mf], bh[0], bh[1]);
                    mma16816(acc[mf][2 * nq + 1], af[mf], bh[2], bh[3]);
                }
            }
        }
        __syncthreads();
    }

    #pragma unroll
    for (int mf = 0; mf < 2; ++mf) {
        int r0 = m0 + wm * 32 + mf * 16 + g;
        #pragma unroll
        for (int nj = 0; nj < 4; ++nj) {
            int c = n0 + wn * 32 + nj * 8 + 2 * t;
            float2 bv = *(const float2*)&bias[c];
            *(float2*)&C[(size_t)r0 * DIM_ + c] =
                make_float2(acc[mf][nj][0] + bv.x, acc[mf][nj][1] + bv.y);
            *(float2*)&C[(size_t)(r0 + 8) * DIM_ + c] =
                make_float2(acc[mf][nj][2] + bv.x, acc[mf][nj][3] + bv.y);
        }
    }
}

// ---------------------------------------------------------------------------
// GEMM 2-term hi/lo (output projection) — exact R11 structure.
// ---------------------------------------------------------------------------
#define G2_STAGE 16384
#define G2_WH    8192
#define G2_WL    12288
#define GEMM2_SMEM (3 * G2_STAGE)   // 48 KB

__global__ __launch_bounds__(256, 2)
void gemm2_kernel(const __half* __restrict__ Ah,
                  const __half* __restrict__ Wh,
                  const __half* __restrict__ Wl,
                  const float* __restrict__ bias,
                  float* __restrict__ C) {
    extern __shared__ char sm[];
    const uint32_t sb = (uint32_t)__cvta_generic_to_shared(sm);
    const int tid = threadIdx.x, wid = tid >> 5, lane = tid & 31;
    const int g = lane >> 2, t = lane & 3;
    const int wm = wid & 3, wn = wid >> 2;
    const int n0 = blockIdx.x * 64, m0 = blockIdx.y * 128;

    auto issue = [&](int kb, int st) {
        uint32_t base = sb + (uint32_t)st * G2_STAGE;
        #pragma unroll
        for (int i = 0; i < 2; ++i) {
            int lin = tid + i * 256;
            int row = lin >> 2, c = lin & 3;
            uint32_t off = (uint32_t)(row * 64 + c * 16);
            off ^= (off >> 3) & 0x30;
            cp16(base + off, Ah + (size_t)(m0 + row) * DIM_ + kb * 32 + c * 8);
        }
        {
            int row = tid >> 3, c = tid & 7;
            uint32_t off = (uint32_t)(row * 128 + c * 16);
            off ^= (off >> 3) & 0x70;
            size_t src = (size_t)(kb * 32 + row) * DIM_ + n0 + c * 8;
            cp16(base + G2_WH + off, Wh + src);
            cp16(base + G2_WL + off, Wl + src);
        }
        asm volatile("cp.async.commit_group;");
    };

    float acc[2][4][4];
    #pragma unroll
    for (int i = 0; i < 2; ++i)
        #pragma unroll
        for (int j = 0; j < 4; ++j)
            #pragma unroll
            for (int r = 0; r < 4; ++r) acc[i][j][r] = 0.f;

    const uint32_t aColByte = (uint32_t)((lane >> 4) * 16);
    const uint32_t xr    = (uint32_t)(lane & 7) << 4;
    const uint32_t wRowB = (uint32_t)((lane & 15) * 128);
    const uint32_t wD    = (uint32_t)((lane >> 4) * 16);
    const uint32_t wCol  = (uint32_t)(wn * 64);

    issue(0, 0);
    issue(1, 1);

    for (int kb = 0; kb < 16; ++kb) {
        asm volatile("cp.async.wait_group 1;");
        __syncthreads();
        if (kb + 2 < 16) issue(kb + 2, (kb + 2) % 3);

        uint32_t base = sb + (uint32_t)(kb % 3) * G2_STAGE;
        #pragma unroll
        for (int s = 0; s < 2; ++s) {
            uint32_t af[2][4];
            #pragma unroll
            for (int mf = 0; mf < 2; ++mf) {
                uint32_t off = (uint32_t)((wm * 32 + mf * 16 + (lane & 15)) * 64)
                             + (uint32_t)(s * 32) + aColByte;
                off ^= (off >> 3) & 0x30;
                ldsm4(af[mf], base + off);
            }
            #pragma unroll
            for (int nq = 0; nq < 2; ++nq) {
                uint32_t wo = (uint32_t)(s * 16 * 128) + wRowB +
                              ((wCol + (uint32_t)(nq * 32) + wD) ^ xr);
                uint32_t bh[4], bl[4];
                ldsm4t(bh, base + G2_WH + wo);
                ldsm4t(bl, base + G2_WL + wo);
                #pragma unroll
                for (int mf = 0; mf < 2; ++mf) {
                    mma16816(acc[mf][2 * nq],     af[mf], bh[0], bh[1]);
                    mma16816(acc[mf][2 * nq + 1], af[mf], bh[2], bh[3]);
                    mma16816(acc[mf][2 * nq],     af[mf], bl[0], bl[1]);
                    mma16816(acc[mf][2 * nq + 1], af[mf], bl[2], bl[3]);
                }
            }
        }
        __syncthreads();
    }

    #pragma unroll
    for (int mf = 0; mf < 2; ++mf) {
        int r0 = m0 + wm * 32 + mf * 16 + g;
        #pragma unroll
        for (int nj = 0; nj < 4; ++nj) {
            int c = n0 + wn * 32 + nj * 8 + 2 * t;
            float2 bv = *(const float2*)&bias[c];
            *(float2*)&C[(size_t)r0 * DIM_ + c] =
                make_float2(acc[mf][nj][0] + bv.x, acc[mf][nj][1] + bv.y);
            *(float2*)&C[(size_t)(r0 + 8) * DIM_ + c] =
                make_float2(acc[mf][nj][2] + bv.x, acc[mf][nj][3] + bv.y);
        }
    }
}

// ---------------------------------------------------------------------------
// FA2 on mma.sync fp16 — R11 structure, but l on the idle FMA pipe
// (fp32 scalar adds + quad shuffle, R7-style) instead of the ones-mma.
// ---------------------------------------------------------------------------
__global__ __launch_bounds__(256, 2)
void attn_mma_kernel(const float* __restrict__ Lp, const float* __restrict__ Qp,
                     __half* __restrict__ Xh) {
    __shared__ __half KH[2][64 * 64];   // [buf][row][d]

    const int tid  = threadIdx.x;
    const int wid  = tid >> 5;
    const int lane = tid & 31;
    const int g = lane >> 2, t = lane & 3;
    const int qb = blockIdx.x, h = blockIdx.y, b = blockIdx.z;
    const float scale = 0.00552427172801990775f * 1.44269504088896341f;

    const uint32_t khb = (uint32_t)__cvta_generic_to_shared(KH);

    uint32_t qa[4][4];
    {
        const float* qbase =
            Qp + ((size_t)b * LQ_ + (size_t)qb * 128 + wid * 16) * DIM_ + h * DK_;
        #pragma unroll
        for (int s = 0; s < 4; ++s) {
            int d0 = 16 * s + 2 * t;
            float2 v0 = *(const float2*)&qbase[(size_t)g * DIM_ + d0];
            float2 v1 = *(const float2*)&qbase[(size_t)(g + 8) * DIM_ + d0];
            float2 v2 = *(const float2*)&qbase[(size_t)g * DIM_ + d0 + 8];
            float2 v3 = *(const float2*)&qbase[(size_t)(g + 8) * DIM_ + d0 + 8];
            qa[s][0] = pack_h2(v0.x * scale, v0.y * scale);
            qa[s][1] = pack_h2(v1.x * scale, v1.y * scale);
            qa[s][2] = pack_h2(v2.x * scale, v2.y * scale);
            qa[s][3] = pack_h2(v3.x * scale, v3.y * scale);
        }
    }

    const int lr0 = tid >> 4;          // 0..15
    const int ld4 = (tid & 15) * 4;    // 0..60
    const float* lbase = Lp + (size_t)b * LK_ * DIM_ + h * DK_;

    float4 pf[4];
    #pragma unroll
    for (int it = 0; it < 4; ++it)
        pf[it] = *(const float4*)&lbase[(size_t)(lr0 + it * 16) * DIM_ + ld4];

    auto store_half = [&](int buf) {
        #pragma unroll
        for (int it = 0; it < 4; ++it) {
            int r = lr0 + it * 16;
            uint32_t off = (uint32_t)(r * 128 + ld4 * 2);
            off = off ^ ((off >> 3) & 0x70);
            *(uint2*)((char*)KH[buf] + off) =
                make_uint2(pack_h2(pf[it].x, pf[it].y), pack_h2(pf[it].z, pf[it].w));
        }
    };
    auto load_half = [&](int j) {
        #pragma unroll
        for (int it = 0; it < 4; ++it)
            pf[it] = *(const float4*)
                &lbase[(size_t)(j * 64 + lr0 + it * 16) * DIM_ + ld4];
    };

    float oacc[8][4];
    #pragma unroll
    for (int i = 0; i < 8; ++i)
        #pragma unroll
        for (int j = 0; j < 4; ++j) oacc[i][j] = 0.f;
    float lacc0 = 0.f, lacc1 = 0.f;   // fp32 l on the idle FMA pipe

    const uint32_t sXor  = (uint32_t)(lane & 7) << 4;
    const uint32_t sRow  = (uint32_t)(lane & 7) * 128;
    const uint32_t sOff0 = sRow + ((((uint32_t)(lane >> 3)) * 16 +  0) ^ sXor);
    const uint32_t sOff1 = sRow + ((((uint32_t)(lane >> 3)) * 16 + 64) ^ sXor);
    const uint32_t vRow  = (uint32_t)(lane & 15) * 128;
    const uint32_t vD    = (uint32_t)(lane >> 4) * 16;

    store_half(0);
    load_half(1);
    __syncthreads();

    for (int i = 0; i < 32; ++i) {
        const uint32_t bo = (uint32_t)((i & 1) * 8192);

        // ---- S = Q K^T, nf-pair interleaved ----
        float sacc[8][4];
        #pragma unroll
        for (int nf = 0; nf < 8; ++nf) {
            sacc[nf][0] = 0.f; sacc[nf][1] = 0.f;
            sacc[nf][2] = 0.f; sacc[nf][3] = 0.f;
        }
        #pragma unroll
        for (int np = 0; np < 4; ++np) {
            uint32_t bA[8], bB[8];
            uint32_t base0 = khb + bo + (uint32_t)(2 * np * 1024);
            ldsm4(bA + 0, base0 + sOff0);
            ldsm4(bA + 4, base0 + sOff1);
            ldsm4(bB + 0, base0 + 1024 + sOff0);
            ldsm4(bB + 4, base0 + 1024 + sOff1);
            #pragma unroll
            for (int s = 0; s < 4; ++s) {
                mma16816(sacc[2 * np],     qa[s], bA[2 * s], bA[2 * s + 1]);
                mma16816(sacc[2 * np + 1], qa[s], bB[2 * s], bB[2 * s + 1]);
            }
        }

        // ---- P = exp2(S) (fp32 MUFU); l += fp32 adds; O += P V ----
        #pragma unroll
        for (int u = 0; u < 4; ++u) {
            float e0 = ex2f(sacc[2 * u][0]),     e1 = ex2f(sacc[2 * u][1]);
            float e2 = ex2f(sacc[2 * u][2]),     e3 = ex2f(sacc[2 * u][3]);
            float e4 = ex2f(sacc[2 * u + 1][0]), e5 = ex2f(sacc[2 * u + 1][1]);
            float e6 = ex2f(sacc[2 * u + 1][2]), e7 = ex2f(sacc[2 * u + 1][3]);
            lacc0 += (e0 + e1) + (e4 + e5);
            lacc1 += (e2 + e3) + (e6 + e7);
            uint32_t pa[4];
            pa[0] = pack_h2(e0, e1);
            pa[1] = pack_h2(e2, e3);
            pa[2] = pack_h2(e4, e5);
            pa[3] = pack_h2(e6, e7);
            #pragma unroll
            for (int dfp = 0; dfp < 4; ++dfp) {
                uint32_t voff = bo + vRow + (uint32_t)(u * 2048)
                              + (((uint32_t)(dfp * 32) + vD) ^ sXor);
                uint32_t vh[4];
                ldsm4t(vh, khb + voff);
                mma16816(oacc[2 * dfp],     pa, vh[0], vh[1]);
                mma16816(oacc[2 * dfp + 1], pa, vh[2], vh[3]);
            }
        }

        if (i < 31) {
            store_half((i + 1) & 1);
            if (i < 30) load_half(i + 2);
            __syncthreads();
        }
    }

    // ---- quad reduce l over the 4 t-lanes ----
    lacc0 += __shfl_xor_sync(0xffffffffu, lacc0, 1);
    lacc0 += __shfl_xor_sync(0xffffffffu, lacc0, 2);
    lacc1 += __shfl_xor_sync(0xffffffffu, lacc1, 1);
    lacc1 += __shfl_xor_sync(0xffffffffu, lacc1, 2);
    float inv0 = 1.f / lacc0, inv1 = 1.f / lacc1;

    size_t r0 = ((size_t)b * LQ_ + (size_t)qb * 128 + wid * 16 + g) * DIM_ + h * DK_;
    size_t r1 = r0 + 8 * DIM_;
    #pragma unroll
    for (int df = 0; df < 8; ++df) {
        int c = df * 8 + 2 * t;
        *(uint32_t*)((char*)Xh + (r0 + c) * 2) =
            pack_h2(oacc[df][0] * inv0, oacc[df][1] * inv0);
        *(uint32_t*)((char*)Xh + (r1 + c) * 2) =
            pack_h2(oacc[df][2] * inv1, oacc[df][3] * inv1);
    }
}

// ---------------------------------------------------------------------------
extern "C" void kernel_launch(void* const* d_in, const int* in_sizes, int n_in,
                              void* d_out, int out_size) {
    const float* L  = (const float*)d_in[0];
    const float* G  = (const float*)d_in[1];
    const float* Wq = (const float*)d_in[2];
    const float* bq = (const float*)d_in[3];
    const float* Wo = (const float*)d_in[4];
    const float* bo = (const float*)d_in[5];
    float* out = (float*)d_out;

    float* qbuf;
    __half *gh, *xh, *wqh, *woh, *wol;
    cudaGetSymbolAddress((void**)&qbuf, g_q);
    cudaGetSymbolAddress((void**)&gh,  g_gh);
    cudaGetSymbolAddress((void**)&xh,  g_xh);
    cudaGetSymbolAddress((void**)&wqh, g_wqh);
    cudaGetSymbolAddress((void**)&woh, g_woh);
    cudaGetSymbolAddress((void**)&wol, g_wol);

    cudaFuncSetAttribute(gemm1_kernel,
                         cudaFuncAttributeMaxDynamicSharedMemorySize, GEMM1_SMEM);
    cudaFuncSetAttribute(gemm2_kernel,
                         cudaFuncAttributeMaxDynamicSharedMemorySize, GEMM2_SMEM);

    dim3 gGemm(DIM_ / 64, M_ / 128);            // (8, 32) = 256 CTAs
    dim3 gAttn(LQ_ / 128, H_, B_);              // 256 CTAs
    int prepBlocks = (NG + 2 * NW + 255) / 256;

    prep_kernel<<<prepBlocks, 256>>>(G, Wq, Wo);
    gemm1_kernel<<<gGemm, 256, GEMM1_SMEM>>>(gh, wqh, bq, qbuf);
    attn_mma_kernel<<<gAttn, 256>>>(L, qbuf, xh);
    gemm2_kernel<<<gGemm, 256, GEMM2_SMEM>>>(xh, woh, wol, bo, out);
}

// round 14
// speedup vs baseline: 1.0992x; 1.0992x over previous
#include <cuda_runtime.h>
#include <cuda_fp16.h>
#include <stdint.h>

#define B_   16
#define LK_  2048
#define LQ_  256
#define DIM_ 512
#define H_   8
#define DK_  64
#define M_   (B_ * LQ_)     // 4096

// ---------------- helpers ----------------
__device__ __forceinline__ uint32_t pack_h2(float x, float y) {
    __half2 h = __float22half2_rn(make_float2(x, y));
    return *(uint32_t*)&h;
}
__device__ __forceinline__ void pack_split_h(float x, float y,
                                             uint32_t& hi, uint32_t& lo) {
    __half2 h = __float22half2_rn(make_float2(x, y));
    float2 hf = __half22float2(h);
    __half2 l = __float22half2_rn(make_float2(x - hf.x, y - hf.y));
    hi = *(uint32_t*)&h;
    lo = *(uint32_t*)&l;
}
// exp2 of packed fp16x2 (direct on the f16 S fragment halves)
__device__ __forceinline__ uint32_t ex2h2(uint32_t x) {
    uint32_t r; asm("ex2.approx.f16x2 %0, %1;" : "=r"(r) : "r"(x)); return r;
}
__device__ __forceinline__ void ldsm4(uint32_t* r, uint32_t addr) {
    asm volatile("ldmatrix.sync.aligned.m8n8.x4.shared.b16 {%0,%1,%2,%3}, [%4];"
        : "=r"(r[0]), "=r"(r[1]), "=r"(r[2]), "=r"(r[3]) : "r"(addr));
}
__device__ __forceinline__ void ldsm4t(uint32_t* r, uint32_t addr) {
    asm volatile("ldmatrix.sync.aligned.m8n8.x4.trans.shared.b16 {%0,%1,%2,%3}, [%4];"
        : "=r"(r[0]), "=r"(r[1]), "=r"(r[2]), "=r"(r[3]) : "r"(addr));
}
// fp32-accumulator mma
__device__ __forceinline__ void mma16816(float* c, const uint32_t* a,
                                         uint32_t b0, uint32_t b1) {
    asm volatile("mma.sync.aligned.m16n8k16.row.col.f32.f16.f16.f32 "
        "{%0,%1,%2,%3}, {%4,%5,%6,%7}, {%8,%9}, {%0,%1,%2,%3};"
        : "+f"(c[0]), "+f"(c[1]), "+f"(c[2]), "+f"(c[3])
        : "r"(a[0]), "r"(a[1]), "r"(a[2]), "r"(a[3]), "r"(b0), "r"(b1));
}
// fp16-accumulator mma (for S: 2x rate on most tensor implementations;
// D fragment {d0,d1} is exactly the A-fragment half-pair layout)
__device__ __forceinline__ void mma16816h(uint32_t* c, const uint32_t* a,
                                          uint32_t b0, uint32_t b1) {
    asm volatile("mma.sync.aligned.m16n8k16.row.col.f16.f16.f16.f16 "
        "{%0,%1}, {%2,%3,%4,%5}, {%6,%7}, {%0,%1};"
        : "+r"(c[0]), "+r"(c[1])
        : "r"(a[0]), "r"(a[1]), "r"(a[2]), "r"(a[3]), "r"(b0), "r"(b1));
}
__device__ __forceinline__ void cp16(uint32_t dst, const void* src) {
    asm volatile("cp.async.cg.shared.global [%0], [%1], 16;" :: "r"(dst), "l"(src));
}

// ---------------- scratch (__device__ globals) ----------------
__device__ float  g_q  [M_ * DIM_];
__device__ __half g_gh [M_ * DIM_];
__device__ __half g_xh [M_ * DIM_];
__device__ __half g_wqh[DIM_ * DIM_];
__device__ __half g_woh[DIM_ * DIM_], g_wol[DIM_ * DIM_];

// ---------------------------------------------------------------------------
// Prep: G -> fp16; Wq -> fp16 (single); Wo -> fp16 hi/lo
// ---------------------------------------------------------------------------
#define NG (M_ * DIM_ / 2)
#define NW (DIM_ * DIM_ / 2)

__global__ void prep_kernel(const float* __restrict__ G,
                            const float* __restrict__ Wq,
                            const float* __restrict__ Wo) {
    int i = blockIdx.x * blockDim.x + threadIdx.x;
    if (i < NG) {
        float2 v = ((const float2*)G)[i];
        ((uint32_t*)g_gh)[i] = pack_h2(v.x, v.y);
    } else if (i < NG + NW) {
        int j = i - NG;
        float2 v = ((const float2*)Wq)[j];
        ((uint32_t*)g_wqh)[j] = pack_h2(v.x, v.y);
    } else if (i < NG + 2 * NW) {
        int j = i - NG - NW;
        float2 v = ((const float2*)Wo)[j];
        uint32_t h, l;
        pack_split_h(v.x, v.y, h, l);
        ((uint32_t*)g_woh)[j] = h; ((uint32_t*)g_wol)[j] = l;
    }
}

// ---------------------------------------------------------------------------
// GEMM 1-term (Q projection) — exact R11 structure.
// ---------------------------------------------------------------------------
#define G1_STAGE 12288
#define G1_WH    8192
#define GEMM1_SMEM (3 * G1_STAGE)   // 36 KB

__global__ __launch_bounds__(256, 2)
void gemm1_kernel(const __half* __restrict__ Ah,
                  const __half* __restrict__ Wh,
                  const float* __restrict__ bias,
                  float* __restrict__ C) {
    extern __shared__ char sm[];
    const uint32_t sb = (uint32_t)__cvta_generic_to_shared(sm);
    const int tid = threadIdx.x, wid = tid >> 5, lane = tid & 31;
    const int g = lane >> 2, t = lane & 3;
    const int wm = wid & 3, wn = wid >> 2;
    const int n0 = blockIdx.x * 64, m0 = blockIdx.y * 128;

    auto issue = [&](int kb, int st) {
        uint32_t base = sb + (uint32_t)st * G1_STAGE;
        #pragma unroll
        for (int i = 0; i < 2; ++i) {
            int lin = tid + i * 256;
            int row = lin >> 2, c = lin & 3;
            uint32_t off = (uint32_t)(row * 64 + c * 16);
            off ^= (off >> 3) & 0x30;
            cp16(base + off, Ah + (size_t)(m0 + row) * DIM_ + kb * 32 + c * 8);
        }
        {
            int row = tid >> 3, c = tid & 7;
            uint32_t off = (uint32_t)(row * 128 + c * 16);
            off ^= (off >> 3) & 0x70;
            cp16(base + G1_WH + off, Wh + (size_t)(kb * 32 + row) * DIM_ + n0 + c * 8);
        }
        asm volatile("cp.async.commit_group;");
    };

    float acc[2][4][4];
    #pragma unroll
    for (int i = 0; i < 2; ++i)
        #pragma unroll
        for (int j = 0; j < 4; ++j)
            #pragma unroll
            for (int r = 0; r < 4; ++r) acc[i][j][r] = 0.f;

    const uint32_t aColByte = (uint32_t)((lane >> 4) * 16);
    const uint32_t xr    = (uint32_t)(lane & 7) << 4;
    const uint32_t wRowB = (uint32_t)((lane & 15) * 128);
    const uint32_t wD    = (uint32_t)((lane >> 4) * 16);
    const uint32_t wCol  = (uint32_t)(wn * 64);

    issue(0, 0);
    issue(1, 1);

    for (int kb = 0; kb < 16; ++kb) {
        asm volatile("cp.async.wait_group 1;");
        __syncthreads();
        if (kb + 2 < 16) issue(kb + 2, (kb + 2) % 3);

        uint32_t base = sb + (uint32_t)(kb % 3) * G1_STAGE;
        #pragma unroll
        for (int s = 0; s < 2; ++s) {
            uint32_t af[2][4];
            #pragma unroll
            for (int mf = 0; mf < 2; ++mf) {
                uint32_t off = (uint32_t)((wm * 32 + mf * 16 + (lane & 15)) * 64)
                             + (uint32_t)(s * 32) + aColByte;
                off ^= (off >> 3) & 0x30;
                ldsm4(af[mf], base + off);
            }
            #pragma unroll
            for (int nq = 0; nq < 2; ++nq) {
                uint32_t wo = (uint32_t)(s * 16 * 128) + wRowB +
                              ((wCol + (uint32_t)(nq * 32) + wD) ^ xr);
                uint32_t bh[4];
                ldsm4t(bh, base + G1_WH + wo);
                #pragma unroll
                for (int mf = 0; mf < 2; ++mf) {
                    mma16816(acc[mf][2 * nq],     af[mf], bh[0], bh[1]);
                    mma16816(acc[mf][2 * nq + 1], af[mf], bh[2], bh[3]);
                }
            }
        }
        __syncthreads();
    }

    #pragma unroll
    for (int mf = 0; mf < 2; ++mf) {
        int r0 = m0 + wm * 32 + mf * 16 + g;
        #pragma unroll
        for (int nj = 0; nj < 4; ++nj) {
            int c = n0 + wn * 32 + nj * 8 + 2 * t;
            float2 bv = *(const float2*)&bias[c];
            *(float2*)&C[(size_t)r0 * DIM_ + c] =
                make_float2(acc[mf][nj][0] + bv.x, acc[mf][nj][1] + bv.y);
            *(float2*)&C[(size_t)(r0 + 8) * DIM_ + c] =
                make_float2(acc[mf][nj][2] + bv.x, acc[mf][nj][3] + bv.y);
        }
    }
}

// ---------------------------------------------------------------------------
// GEMM 2-term hi/lo (output projection) — exact R11 structure.
// ---------------------------------------------------------------------------
#define G2_STAGE 16384
#define G2_WH    8192
#define G2_WL    12288
#define GEMM2_SMEM (3 * G2_STAGE)   // 48 KB

__global__ __launch_bounds__(256, 2)
void gemm2_kernel(const __half* __restrict__ Ah,
                  const __half* __restrict__ Wh,
                  const __half* __restrict__ Wl,
                  const float* __restrict__ bias,
                  float* __restrict__ C) {
    extern __shared__ char sm[];
    const uint32_t sb = (uint32_t)__cvta_generic_to_shared(sm);
    const int tid = threadIdx.x, wid = tid >> 5, lane = tid & 31;
    const int g = lane >> 2, t = lane & 3;
    const int wm = wid & 3, wn = wid >> 2;
    const int n0 = blockIdx.x * 64, m0 = blockIdx.y * 128;

    auto issue = [&](int kb, int st) {
        uint32_t base = sb + (uint32_t)st * G2_STAGE;
        #pragma unroll
        for (int i = 0; i < 2; ++i) {
            int lin = tid + i * 256;
            int row = lin >> 2, c = lin & 3;
            uint32_t off = (uint32_t)(row * 64 + c * 16);
            off ^= (off >> 3) & 0x30;
            cp16(base + off, Ah + (size_t)(m0 + row) * DIM_ + kb * 32 + c * 8);
        }
        {
            int row = tid >> 3, c = tid & 7;
            uint32_t off = (uint32_t)(row * 128 + c * 16);
            off ^= (off >> 3) & 0x70;
            size_t src = (size_t)(kb * 32 + row) * DIM_ + n0 + c * 8;
            cp16(base + G2_WH + off, Wh + src);
            cp16(base + G2_WL + off, Wl + src);
        }
        asm volatile("cp.async.commit_group;");
    };

    float acc[2][4][4];
    #pragma unroll
    for (int i = 0; i < 2; ++i)
        #pragma unroll
        for (int j = 0; j < 4; ++j)
            #pragma unroll
            for (int r = 0; r < 4; ++r) acc[i][j][r] = 0.f;

    const uint32_t aColByte = (uint32_t)((lane >> 4) * 16);
    const uint32_t xr    = (uint32_t)(lane & 7) << 4;
    const uint32_t wRowB = (uint32_t)((lane & 15) * 128);
    const uint32_t wD    = (uint32_t)((lane >> 4) * 16);
    const uint32_t wCol  = (uint32_t)(wn * 64);

    issue(0, 0);
    issue(1, 1);

    for (int kb = 0; kb < 16; ++kb) {
        asm volatile("cp.async.wait_group 1;");
        __syncthreads();
        if (kb + 2 < 16) issue(kb + 2, (kb + 2) % 3);

        uint32_t base = sb + (uint32_t)(kb % 3) * G2_STAGE;
        #pragma unroll
        for (int s = 0; s < 2; ++s) {
            uint32_t af[2][4];
            #pragma unroll
            for (int mf = 0; mf < 2; ++mf) {
                uint32_t off = (uint32_t)((wm * 32 + mf * 16 + (lane & 15)) * 64)
                             + (uint32_t)(s * 32) + aColByte;
                off ^= (off >> 3) & 0x30;
                ldsm4(af[mf], base + off);
            }
            #pragma unroll
            for (int nq = 0; nq < 2; ++nq) {
                uint32_t wo = (uint32_t)(s * 16 * 128) + wRowB +
                              ((wCol + (uint32_t)(nq * 32) + wD) ^ xr);
                uint32_t bh[4], bl[4];
                ldsm4t(bh, base + G2_WH + wo);
                ldsm4t(bl, base + G2_WL + wo);
                #pragma unroll
                for (int mf = 0; mf < 2; ++mf) {
                    mma16816(acc[mf][2 * nq],     af[mf], bh[0], bh[1]);
                    mma16816(acc[mf][2 * nq + 1], af[mf], bh[2], bh[3]);
                    mma16816(acc[mf][2 * nq],     af[mf], bl[0], bl[1]);
                    mma16816(acc[mf][2 * nq + 1], af[mf], bl[2], bl[3]);
                }
            }
        }
        __syncthreads();
    }

    #pragma unroll
    for (int mf = 0; mf < 2; ++mf) {
        int r0 = m0 + wm * 32 + mf * 16 + g;
        #pragma unroll
        for (int nj = 0; nj < 4; ++nj) {
            int c = n0 + wn * 32 + nj * 8 + 2 * t;
            float2 bv = *(const float2*)&bias[c];
            *(float2*)&C[(size_t)r0 * DIM_ + c] =
                make_float2(acc[mf][nj][0] + bv.x, acc[mf][nj][1] + bv.y);
            *(float2*)&C[(size_t)(r0 + 8) * DIM_ + c] =
                make_float2(acc[mf][nj][2] + bv.x, acc[mf][nj][3] + bv.y);
        }
    }
}

// ---------------------------------------------------------------------------
// FA2 on mma.sync — R11 structure, with S on fp16-accumulator HMMA.
// S fragment halves feed ex2.approx.f16x2 directly (no cvt/pack stage);
// l via ones-mma (fp32) as in R11; PV accumulates fp32.
// ---------------------------------------------------------------------------
#define ONES_H2 0x3C003C00u

__global__ __launch_bounds__(256, 2)
void attn_mma_kernel(const float* __restrict__ Lp, const float* __restrict__ Qp,
                     __half* __restrict__ Xh) {
    __shared__ __half KH[2][64 * 64];   // [buf][row][d]

    const int tid  = threadIdx.x;
    const int wid  = tid >> 5;
    const int lane = tid & 31;
    const int g = lane >> 2, t = lane & 3;
    const int qb = blockIdx.x, h = blockIdx.y, b = blockIdx.z;
    const float scale = 0.00552427172801990775f * 1.44269504088896341f;

    const uint32_t khb = (uint32_t)__cvta_generic_to_shared(KH);

    uint32_t qa[4][4];
    {
        const float* qbase =
            Qp + ((size_t)b * LQ_ + (size_t)qb * 128 + wid * 16) * DIM_ + h * DK_;
        #pragma unroll
        for (int s = 0; s < 4; ++s) {
            int d0 = 16 * s + 2 * t;
            float2 v0 = *(const float2*)&qbase[(size_t)g * DIM_ + d0];
            float2 v1 = *(const float2*)&qbase[(size_t)(g + 8) * DIM_ + d0];
            float2 v2 = *(const float2*)&qbase[(size_t)g * DIM_ + d0 + 8];
            float2 v3 = *(const float2*)&qbase[(size_t)(g + 8) * DIM_ + d0 + 8];
            qa[s][0] = pack_h2(v0.x * scale, v0.y * scale);
            qa[s][1] = pack_h2(v1.x * scale, v1.y * scale);
            qa[s][2] = pack_h2(v2.x * scale, v2.y * scale);
            qa[s][3] = pack_h2(v3.x * scale, v3.y * scale);
        }
    }

    const int lr0 = tid >> 4;          // 0..15
    const int ld4 = (tid & 15) * 4;    // 0..60
    const float* lbase = Lp + (size_t)b * LK_ * DIM_ + h * DK_;

    float4 pf[4];
    #pragma unroll
    for (int it = 0; it < 4; ++it)
        pf[it] = *(const float4*)&lbase[(size_t)(lr0 + it * 16) * DIM_ + ld4];

    auto store_half = [&](int buf) {
        #pragma unroll
        for (int it = 0; it < 4; ++it) {
            int r = lr0 + it * 16;
            uint32_t off = (uint32_t)(r * 128 + ld4 * 2);
            off = off ^ ((off >> 3) & 0x70);
            *(uint2*)((char*)KH[buf] + off) =
                make_uint2(pack_h2(pf[it].x, pf[it].y), pack_h2(pf[it].z, pf[it].w));
        }
    };
    auto load_half = [&](int j) {
        #pragma unroll
        for (int it = 0; it < 4; ++it)
            pf[it] = *(const float4*)
                &lbase[(size_t)(j * 64 + lr0 + it * 16) * DIM_ + ld4];
    };

    float oacc[8][4];
    #pragma unroll
    for (int i = 0; i < 8; ++i)
        #pragma unroll
        for (int j = 0; j < 4; ++j) oacc[i][j] = 0.f;
    float lfrag[4] = {0.f, 0.f, 0.f, 0.f};

    const uint32_t sXor  = (uint32_t)(lane & 7) << 4;
    const uint32_t sRow  = (uint32_t)(lane & 7) * 128;
    const uint32_t sOff0 = sRow + ((((uint32_t)(lane >> 3)) * 16 +  0) ^ sXor);
    const uint32_t sOff1 = sRow + ((((uint32_t)(lane >> 3)) * 16 + 64) ^ sXor);
    const uint32_t vRow  = (uint32_t)(lane & 15) * 128;
    const uint32_t vD    = (uint32_t)(lane >> 4) * 16;

    store_half(0);
    load_half(1);
    __syncthreads();

    for (int i = 0; i < 32; ++i) {
        const uint32_t bo = (uint32_t)((i & 1) * 8192);

        // ---- S = Q K^T in fp16 accumulators, nf-pair interleaved ----
        uint32_t sacc[8][2];
        #pragma unroll
        for (int nf = 0; nf < 8; ++nf) { sacc[nf][0] = 0u; sacc[nf][1] = 0u; }
        #pragma unroll
        for (int np = 0; np < 4; ++np) {
            uint32_t bA[8], bB[8];
            uint32_t base0 = khb + bo + (uint32_t)(2 * np * 1024);
            ldsm4(bA + 0, base0 + sOff0);
            ldsm4(bA + 4, base0 + sOff1);
            ldsm4(bB + 0, base0 + 1024 + sOff0);
            ldsm4(bB + 4, base0 + 1024 + sOff1);
            #pragma unroll
            for (int s = 0; s < 4; ++s) {
                mma16816h(sacc[2 * np],     qa[s], bA[2 * s], bA[2 * s + 1]);
                mma16816h(sacc[2 * np + 1], qa[s], bB[2 * s], bB[2 * s + 1]);
            }
        }

        // ---- P = exp2(S) directly on f16x2 halves; l += P@ones; O += P V ----
        #pragma unroll
        for (int u = 0; u < 4; ++u) {
            uint32_t pa[4];
            pa[0] = ex2h2(sacc[2 * u][0]);
            pa[1] = ex2h2(sacc[2 * u][1]);
            pa[2] = ex2h2(sacc[2 * u + 1][0]);
            pa[3] = ex2h2(sacc[2 * u + 1][1]);
            mma16816(lfrag, pa, ONES_H2, ONES_H2);
            #pragma unroll
            for (int dfp = 0; dfp < 4; ++dfp) {
                uint32_t voff = bo + vRow + (uint32_t)(u * 2048)
                              + (((uint32_t)(dfp * 32) + vD) ^ sXor);
                uint32_t vh[4];
                ldsm4t(vh, khb + voff);
                mma16816(oacc[2 * dfp],     pa, vh[0], vh[1]);
                mma16816(oacc[2 * dfp + 1], pa, vh[2], vh[3]);
            }
        }

        if (i < 31) {
            store_half((i + 1) & 1);
            if (i < 30) load_half(i + 2);
            __syncthreads();
        }
    }

    float inv0 = 1.f / lfrag[0], inv1 = 1.f / lfrag[2];

    size_t r0 = ((size_t)b * LQ_ + (size_t)qb * 128 + wid * 16 + g) * DIM_ + h * DK_;
    size_t r1 = r0 + 8 * DIM_;
    #pragma unroll
    for (int df = 0; df < 8; ++df) {
        int c = df * 8 + 2 * t;
        *(uint32_t*)((char*)Xh + (r0 + c) * 2) =
            pack_h2(oacc[df][0] * inv0, oacc[df][1] * inv0);
        *(uint32_t*)((char*)Xh + (r1 + c) * 2) =
            pack_h2(oacc[df][2] * inv1, oacc[df][3] * inv1);
    }
}

// ---------------------------------------------------------------------------
extern "C" void kernel_launch(void* const* d_in, const int* in_sizes, int n_in,
                              void* d_out, int out_size) {
    const float* L  = (const float*)d_in[0];
    const float* G  = (const float*)d_in[1];
    const float* Wq = (const float*)d_in[2];
    const float* bq = (const float*)d_in[3];
    const float* Wo = (const float*)d_in[4];
    const float* bo = (const float*)d_in[5];
    float* out = (float*)d_out;

    float* qbuf;
    __half *gh, *xh, *wqh, *woh, *wol;
    cudaGetSymbolAddress((void**)&qbuf, g_q);
    cudaGetSymbolAddress((void**)&gh,  g_gh);
    cudaGetSymbolAddress((void**)&xh,  g_xh);
    cudaGetSymbolAddress((void**)&wqh, g_wqh);
    cudaGetSymbolAddress((void**)&woh, g_woh);
    cudaGetSymbolAddress((void**)&wol, g_wol);

    cudaFuncSetAttribute(gemm1_kernel,
                         cudaFuncAttributeMaxDynamicSharedMemorySize, GEMM1_SMEM);
    cudaFuncSetAttribute(gemm2_kernel,
                         cudaFuncAttributeMaxDynamicSharedMemorySize, GEMM2_SMEM);

    dim3 gGemm(DIM_ / 64, M_ / 128);            // (8, 32) = 256 CTAs
    dim3 gAttn(LQ_ / 128, H_, B_);              // 256 CTAs
    int prepBlocks = (NG + 2 * NW + 255) / 256;

    prep_kernel<<<prepBlocks, 256>>>(G, Wq, Wo);
    gemm1_kernel<<<gGemm, 256, GEMM1_SMEM>>>(gh, wqh, bq, qbuf);
    attn_mma_kernel<<<gAttn, 256>>>(L, qbuf, xh);
    gemm2_kernel<<<gGemm, 256, GEMM2_SMEM>>>(xh, woh, wol, bo, out);
}

// round 15
// speedup vs baseline: 1.1032x; 1.0036x over previous
#include <cuda_runtime.h>
#include <cuda_fp16.h>
#include <stdint.h>

#define B_   16
#define LK_  2048
#define LQ_  256
#define DIM_ 512
#define H_   8
#define DK_  64
#define M_   (B_ * LQ_)     // 4096

// q scale folded with log2(e): S lands in log2 domain
#define QSCALE (0.00552427172801990775f * 1.44269504088896341f)

// ---------------- helpers ----------------
__device__ __forceinline__ uint32_t pack_h2(float x, float y) {
    __half2 h = __float22half2_rn(make_float2(x, y));
    return *(uint32_t*)&h;
}
__device__ __forceinline__ void pack_split_h(float x, float y,
                                             uint32_t& hi, uint32_t& lo) {
    __half2 h = __float22half2_rn(make_float2(x, y));
    float2 hf = __half22float2(h);
    __half2 l = __float22half2_rn(make_float2(x - hf.x, y - hf.y));
    hi = *(uint32_t*)&h;
    lo = *(uint32_t*)&l;
}
__device__ __forceinline__ uint32_t ex2h2(uint32_t x) {
    uint32_t r; asm("ex2.approx.f16x2 %0, %1;" : "=r"(r) : "r"(x)); return r;
}
__device__ __forceinline__ void ldsm4(uint32_t* r, uint32_t addr) {
    asm volatile("ldmatrix.sync.aligned.m8n8.x4.shared.b16 {%0,%1,%2,%3}, [%4];"
        : "=r"(r[0]), "=r"(r[1]), "=r"(r[2]), "=r"(r[3]) : "r"(addr));
}
__device__ __forceinline__ void ldsm4t(uint32_t* r, uint32_t addr) {
    asm volatile("ldmatrix.sync.aligned.m8n8.x4.trans.shared.b16 {%0,%1,%2,%3}, [%4];"
        : "=r"(r[0]), "=r"(r[1]), "=r"(r[2]), "=r"(r[3]) : "r"(addr));
}
__device__ __forceinline__ void mma16816(float* c, const uint32_t* a,
                                         uint32_t b0, uint32_t b1) {
    asm volatile("mma.sync.aligned.m16n8k16.row.col.f32.f16.f16.f32 "
        "{%0,%1,%2,%3}, {%4,%5,%6,%7}, {%8,%9}, {%0,%1,%2,%3};"
        : "+f"(c[0]), "+f"(c[1]), "+f"(c[2]), "+f"(c[3])
        : "r"(a[0]), "r"(a[1]), "r"(a[2]), "r"(a[3]), "r"(b0), "r"(b1));
}
__device__ __forceinline__ void mma16816h(uint32_t* c, const uint32_t* a,
                                          uint32_t b0, uint32_t b1) {
    asm volatile("mma.sync.aligned.m16n8k16.row.col.f16.f16.f16.f16 "
        "{%0,%1}, {%2,%3,%4,%5}, {%6,%7}, {%0,%1};"
        : "+r"(c[0]), "+r"(c[1])
        : "r"(a[0]), "r"(a[1]), "r"(a[2]), "r"(a[3]), "r"(b0), "r"(b1));
}
__device__ __forceinline__ void cp16(uint32_t dst, const void* src) {
    asm volatile("cp.async.cg.shared.global [%0], [%1], 16;" :: "r"(dst), "l"(src));
}

// ---------------- scratch (__device__ globals) ----------------
__device__ __half g_gh [M_ * DIM_];
__device__ __half g_xh [M_ * DIM_];
__device__ __half g_wqh[DIM_ * DIM_];
__device__ __half g_woh[DIM_ * DIM_], g_wol[DIM_ * DIM_];

// ---------------------------------------------------------------------------
// Prep: G -> fp16; Wq -> fp16 (single); Wo -> fp16 hi/lo
// ---------------------------------------------------------------------------
#define NG (M_ * DIM_ / 2)
#define NW (DIM_ * DIM_ / 2)

__global__ void prep_kernel(const float* __restrict__ G,
                            const float* __restrict__ Wq,
                            const float* __restrict__ Wo) {
    int i = blockIdx.x * blockDim.x + threadIdx.x;
    if (i < NG) {
        float2 v = ((const float2*)G)[i];
        ((uint32_t*)g_gh)[i] = pack_h2(v.x, v.y);
    } else if (i < NG + NW) {
        int j = i - NG;
        float2 v = ((const float2*)Wq)[j];
        ((uint32_t*)g_wqh)[j] = pack_h2(v.x, v.y);
    } else if (i < NG + 2 * NW) {
        int j = i - NG - NW;
        float2 v = ((const float2*)Wo)[j];
        uint32_t h, l;
        pack_split_h(v.x, v.y, h, l);
        ((uint32_t*)g_woh)[j] = h; ((uint32_t*)g_wol)[j] = l;
    }
}

// ---------------------------------------------------------------------------
// GEMM 2-term hi/lo (output projection) — exact R11 structure.
// ---------------------------------------------------------------------------
#define G2_STAGE 16384
#define G2_WH    8192
#define G2_WL    12288
#define GEMM2_SMEM (3 * G2_STAGE)   // 48 KB

__global__ __launch_bounds__(256, 2)
void gemm2_kernel(const __half* __restrict__ Ah,
                  const __half* __restrict__ Wh,
                  const __half* __restrict__ Wl,
                  const float* __restrict__ bias,
                  float* __restrict__ C) {
    extern __shared__ char sm[];
    const uint32_t sb = (uint32_t)__cvta_generic_to_shared(sm);
    const int tid = threadIdx.x, wid = tid >> 5, lane = tid & 31;
    const int g = lane >> 2, t = lane & 3;
    const int wm = wid & 3, wn = wid >> 2;
    const int n0 = blockIdx.x * 64, m0 = blockIdx.y * 128;

    auto issue = [&](int kb, int st) {
        uint32_t base = sb + (uint32_t)st * G2_STAGE;
        #pragma unroll
        for (int i = 0; i < 2; ++i) {
            int lin = tid + i * 256;
            int row = lin >> 2, c = lin & 3;
            uint32_t off = (uint32_t)(row * 64 + c * 16);
            off ^= (off >> 3) & 0x30;
            cp16(base + off, Ah + (size_t)(m0 + row) * DIM_ + kb * 32 + c * 8);
        }
        {
            int row = tid >> 3, c = tid & 7;
            uint32_t off = (uint32_t)(row * 128 + c * 16);
            off ^= (off >> 3) & 0x70;
            size_t src = (size_t)(kb * 32 + row) * DIM_ + n0 + c * 8;
            cp16(base + G2_WH + off, Wh + src);
            cp16(base + G2_WL + off, Wl + src);
        }
        asm volatile("cp.async.commit_group;");
    };

    float acc[2][4][4];
    #pragma unroll
    for (int i = 0; i < 2; ++i)
        #pragma unroll
        for (int j = 0; j < 4; ++j)
            #pragma unroll
            for (int r = 0; r < 4; ++r) acc[i][j][r] = 0.f;

    const uint32_t aColByte = (uint32_t)((lane >> 4) * 16);
    const uint32_t xr    = (uint32_t)(lane & 7) << 4;
    const uint32_t wRowB = (uint32_t)((lane & 15) * 128);
    const uint32_t wD    = (uint32_t)((lane >> 4) * 16);
    const uint32_t wCol  = (uint32_t)(wn * 64);

    issue(0, 0);
    issue(1, 1);

    for (int kb = 0; kb < 16; ++kb) {
        asm volatile("cp.async.wait_group 1;");
        __syncthreads();
        if (kb + 2 < 16) issue(kb + 2, (kb + 2) % 3);

        uint32_t base = sb + (uint32_t)(kb % 3) * G2_STAGE;
        #pragma unroll
        for (int s = 0; s < 2; ++s) {
            uint32_t af[2][4];
            #pragma unroll
            for (int mf = 0; mf < 2; ++mf) {
                uint32_t off = (uint32_t)((wm * 32 + mf * 16 + (lane & 15)) * 64)
                             + (uint32_t)(s * 32) + aColByte;
                off ^= (off >> 3) & 0x30;
                ldsm4(af[mf], base + off);
            }
            #pragma unroll
            for (int nq = 0; nq < 2; ++nq) {
                uint32_t wo = (uint32_t)(s * 16 * 128) + wRowB +
                              ((wCol + (uint32_t)(nq * 32) + wD) ^ xr);
                uint32_t bh[4], bl[4];
                ldsm4t(bh, base + G2_WH + wo);
                ldsm4t(bl, base + G2_WL + wo);
                #pragma unroll
                for (int mf = 0; mf < 2; ++mf) {
                    mma16816(acc[mf][2 * nq],     af[mf], bh[0], bh[1]);
                    mma16816(acc[mf][2 * nq + 1], af[mf], bh[2], bh[3]);
                    mma16816(acc[mf][2 * nq],     af[mf], bl[0], bl[1]);
                    mma16816(acc[mf][2 * nq + 1], af[mf], bl[2], bl[3]);
                }
            }
        }
        __syncthreads();
    }

    #pragma unroll
    for (int mf = 0; mf < 2; ++mf) {
        int r0 = m0 + wm * 32 + mf * 16 + g;
        #pragma unroll
        for (int nj = 0; nj < 4; ++nj) {
            int c = n0 + wn * 32 + nj * 8 + 2 * t;
            float2 bv = *(const float2*)&bias[c];
            *(float2*)&C[(size_t)r0 * DIM_ + c] =
                make_float2(acc[mf][nj][0] + bv.x, acc[mf][nj][1] + bv.y);
            *(float2*)&C[(size_t)(r0 + 8) * DIM_ + c] =
                make_float2(acc[mf][nj][2] + bv.x, acc[mf][nj][3] + bv.y);
        }
    }
}

// ---------------------------------------------------------------------------
// Fused Q-projection + FA2 attention.
// Prologue: qa = (G[m0:m0+128] @ Wq[:, h*64:+64] + bq) * QSCALE, computed as a
// 3-stage cp.async mini-gemm whose D-fragments ARE the S-mma A-fragments.
// Mainloop: R14 (fp16-acc S, ex2.f16x2, l via ones-mma, PV fp32).
// smem: union of prologue ring (3 x 12KB) and K double buffer (2 x 8KB).
// ---------------------------------------------------------------------------
#define QP_STAGE 12288
#define QP_W     8192
#define ONES_H2  0x3C003C00u

__global__ __launch_bounds__(256, 2)
void attn_fused_kernel(const float* __restrict__ Lp,
                       const __half* __restrict__ Gh,
                       const __half* __restrict__ Wqh,
                       const float* __restrict__ bq,
                       __half* __restrict__ Xh) {
    __shared__ __align__(128) char smem_raw[3 * QP_STAGE];   // 36 KB

    const int tid  = threadIdx.x;
    const int wid  = tid >> 5;
    const int lane = tid & 31;
    const int g = lane >> 2, t = lane & 3;
    const int qb = blockIdx.x, h = blockIdx.y, b = blockIdx.z;

    const uint32_t sb = (uint32_t)__cvta_generic_to_shared(smem_raw);

    // common lane constants
    const uint32_t xr    = (uint32_t)(lane & 7) << 4;
    const uint32_t wD    = (uint32_t)((lane >> 4) * 16);
    const uint32_t wRowB = (uint32_t)((lane & 15) * 128);
    const uint32_t aColByte = (uint32_t)((lane >> 4) * 16);

    // ======================= Q-projection prologue =======================
    uint32_t qa[4][4];
    {
        const int m0 = (b * 2 + qb) * 128;   // row block in G (b*LQ + qb*128)
        const int n0 = h * DK_;              // head column slice of Wq

        auto issueQ = [&](int kb, int st) {
            uint32_t base = sb + (uint32_t)st * QP_STAGE;
            // A (G): 128 rows x 64B, 512 granules, 2/thread
            #pragma unroll
            for (int i = 0; i < 2; ++i) {
                int lin = tid + i * 256;
                int row = lin >> 2, c = lin & 3;
                uint32_t off = (uint32_t)(row * 64 + c * 16);
                off ^= (off >> 3) & 0x30;
                cp16(base + off, Gh + (size_t)(m0 + row) * DIM_ + kb * 32 + c * 8);
            }
            // W (Wq slice): 32 rows x 128B, 256 granules, 1/thread
            {
                int row = tid >> 3, c = tid & 7;
                uint32_t off = (uint32_t)(row * 128 + c * 16);
                off ^= (off >> 3) & 0x70;
                cp16(base + QP_W + off,
                     Wqh + (size_t)(kb * 32 + row) * DIM_ + n0 + c * 8);
            }
            asm volatile("cp.async.commit_group;");
        };

        float acc[8][4];
        #pragma unroll
        for (int j = 0; j < 8; ++j) {
            acc[j][0] = 0.f; acc[j][1] = 0.f; acc[j][2] = 0.f; acc[j][3] = 0.f;
        }

        issueQ(0, 0);
        issueQ(1, 1);

        for (int kb = 0; kb < 16; ++kb) {
            asm volatile("cp.async.wait_group 1;");
            __syncthreads();
            if (kb + 2 < 16) issueQ(kb + 2, (kb + 2) % 3);

            uint32_t base = sb + (uint32_t)(kb % 3) * QP_STAGE;
            #pragma unroll
            for (int s = 0; s < 2; ++s) {
                // A frag: warp's m16 rows
                uint32_t af[4];
                {
                    uint32_t off = (uint32_t)((wid * 16 + (lane & 15)) * 64)
                                 + (uint32_t)(s * 32) + aColByte;
                    off ^= (off >> 3) & 0x30;
                    ldsm4(af, base + off);
                }
                // W frags over full n64
                #pragma unroll
                for (int nq = 0; nq < 4; ++nq) {
                    uint32_t wo = (uint32_t)(s * 16 * 128) + wRowB +
                                  (((uint32_t)(nq * 32) + wD) ^ xr);
                    uint32_t bh[4];
                    ldsm4t(bh, base + QP_W + wo);
                    mma16816(acc[2 * nq],     af, bh[0], bh[1]);
                    mma16816(acc[2 * nq + 1], af, bh[2], bh[3]);
                }
            }
            __syncthreads();
        }

        // D-fragments -> S-mma A-fragments, with bias + QSCALE
        #pragma unroll
        for (int s = 0; s < 4; ++s) {
            float2 b0 = *(const float2*)&bq[h * DK_ + (2 * s) * 8 + 2 * t];
            float2 b1 = *(const float2*)&bq[h * DK_ + (2 * s + 1) * 8 + 2 * t];
            qa[s][0] = pack_h2((acc[2 * s][0] + b0.x) * QSCALE,
                               (acc[2 * s][1] + b0.y) * QSCALE);
            qa[s][1] = pack_h2((acc[2 * s][2] + b0.x) * QSCALE,
                               (acc[2 * s][3] + b0.y) * QSCALE);
            qa[s][2] = pack_h2((acc[2 * s + 1][0] + b1.x) * QSCALE,
                               (acc[2 * s + 1][1] + b1.y) * QSCALE);
            qa[s][3] = pack_h2((acc[2 * s + 1][2] + b1.x) * QSCALE,
                               (acc[2 * s + 1][3] + b1.y) * QSCALE);
        }
    }
    __syncthreads();   // prologue smem dead; K buffers take over

    // ======================= attention mainloop (R14) =====================
    const int lr0 = tid >> 4;          // 0..15
    const int ld4 = (tid & 15) * 4;    // 0..60
    const float* lbase = Lp + (size_t)b * LK_ * DIM_ + h * DK_;

    float4 pf[4];
    #pragma unroll
    for (int it = 0; it < 4; ++it)
        pf[it] = *(const float4*)&lbase[(size_t)(lr0 + it * 16) * DIM_ + ld4];

    auto store_half = [&](int buf) {
        #pragma unroll
        for (int it = 0; it < 4; ++it) {
            int r = lr0 + it * 16;
            uint32_t off = (uint32_t)(r * 128 + ld4 * 2);
            off = off ^ ((off >> 3) & 0x70);
            *(uint2*)(smem_raw + buf * 8192 + off) =
                make_uint2(pack_h2(pf[it].x, pf[it].y), pack_h2(pf[it].z, pf[it].w));
        }
    };
    auto load_half = [&](int j) {
        #pragma unroll
        for (int it = 0; it < 4; ++it)
            pf[it] = *(const float4*)
                &lbase[(size_t)(j * 64 + lr0 + it * 16) * DIM_ + ld4];
    };

    float oacc[8][4];
    #pragma unroll
    for (int i = 0; i < 8; ++i)
        #pragma unroll
        for (int j = 0; j < 4; ++j) oacc[i][j] = 0.f;
    float lfrag[4] = {0.f, 0.f, 0.f, 0.f};

    const uint32_t sRow  = (uint32_t)(lane & 7) * 128;
    const uint32_t sOff0 = sRow + ((((uint32_t)(lane >> 3)) * 16 +  0) ^ xr);
    const uint32_t sOff1 = sRow + ((((uint32_t)(lane >> 3)) * 16 + 64) ^ xr);
    const uint32_t vRow  = (uint32_t)(lane & 15) * 128;

    store_half(0);
    load_half(1);
    __syncthreads();

    for (int i = 0; i < 32; ++i) {
        const uint32_t bo = (uint32_t)((i & 1) * 8192);

        // ---- S = Q K^T in fp16 accumulators, nf-pair interleaved ----
        uint32_t sacc[8][2];
        #pragma unroll
        for (int nf = 0; nf < 8; ++nf) { sacc[nf][0] = 0u; sacc[nf][1] = 0u; }
        #pragma unroll
        for (int np = 0; np < 4; ++np) {
            uint32_t bA[8], bB[8];
            uint32_t base0 = sb + bo + (uint32_t)(2 * np * 1024);
            ldsm4(bA + 0, base0 + sOff0);
            ldsm4(bA + 4, base0 + sOff1);
            ldsm4(bB + 0, base0 + 1024 + sOff0);
            ldsm4(bB + 4, base0 + 1024 + sOff1);
            #pragma unroll
            for (int s = 0; s < 4; ++s) {
                mma16816h(sacc[2 * np],     qa[s], bA[2 * s], bA[2 * s + 1]);
                mma16816h(sacc[2 * np + 1], qa[s], bB[2 * s], bB[2 * s + 1]);
            }
        }

        // ---- P = exp2(S) on f16x2 halves; l += P@ones; O += P V ----
        #pragma unroll
        for (int u = 0; u < 4; ++u) {
            uint32_t pa[4];
            pa[0] = ex2h2(sacc[2 * u][0]);
            pa[1] = ex2h2(sacc[2 * u][1]);
            pa[2] = ex2h2(sacc[2 * u + 1][0]);
            pa[3] = ex2h2(sacc[2 * u + 1][1]);
            mma16816(lfrag, pa, ONES_H2, ONES_H2);
            #pragma unroll
            for (int dfp = 0; dfp < 4; ++dfp) {
                uint32_t voff = bo + vRow + (uint32_t)(u * 2048)
                              + (((uint32_t)(dfp * 32) + wD) ^ xr);
                uint32_t vh[4];
                ldsm4t(vh, sb + voff);
                mma16816(oacc[2 * dfp],     pa, vh[0], vh[1]);
                mma16816(oacc[2 * dfp + 1], pa, vh[2], vh[3]);
            }
        }

        if (i < 31) {
            store_half((i + 1) & 1);
            if (i < 30) load_half(i + 2);
            __syncthreads();
        }
    }

    float inv0 = 1.f / lfrag[0], inv1 = 1.f / lfrag[2];

    size_t r0 = ((size_t)b * LQ_ + (size_t)qb * 128 + wid * 16 + g) * DIM_ + h * DK_;
    size_t r1 = r0 + 8 * DIM_;
    #pragma unroll
    for (int df = 0; df < 8; ++df) {
        int c = df * 8 + 2 * t;
        *(uint32_t*)((char*)Xh + (r0 + c) * 2) =
            pack_h2(oacc[df][0] * inv0, oacc[df][1] * inv0);
        *(uint32_t*)((char*)Xh + (r1 + c) * 2) =
            pack_h2(oacc[df][2] * inv1, oacc[df][3] * inv1);
    }
}

// ---------------------------------------------------------------------------
extern "C" void kernel_launch(void* const* d_in, const int* in_sizes, int n_in,
                              void* d_out, int out_size) {
    const float* L  = (const float*)d_in[0];
    const float* G  = (const float*)d_in[1];
    const float* Wq = (const float*)d_in[2];
    const float* bq = (const float*)d_in[3];
    const float* Wo = (const float*)d_in[4];
    const float* bo = (const float*)d_in[5];
    float* out = (float*)d_out;

    __half *gh, *xh, *wqh, *woh, *wol;
    cudaGetSymbolAddress((void**)&gh,  g_gh);
    cudaGetSymbolAddress((void**)&xh,  g_xh);
    cudaGetSymbolAddress((void**)&wqh, g_wqh);
    cudaGetSymbolAddress((void**)&woh, g_woh);
    cudaGetSymbolAddress((void**)&wol, g_wol);

    cudaFuncSetAttribute(gemm2_kernel,
                         cudaFuncAttributeMaxDynamicSharedMemorySize, GEMM2_SMEM);

    dim3 gGemm(DIM_ / 64, M_ / 128);            // (8, 32) = 256 CTAs
    dim3 gAttn(LQ_ / 128, H_, B_);              // (2, 8, 16) = 256 CTAs
    int prepBlocks = (NG + 2 * NW + 255) / 256;

    prep_kernel<<<prepBlocks, 256>>>(G, Wq, Wo);
    attn_fused_kernel<<<gAttn, 256>>>(L, gh, wqh, bq, xh);
    gemm2_kernel<<<gGemm, 256, GEMM2_SMEM>>>(xh, woh, wol, bo, out);
}

// round 16
// speedup vs baseline: 1.1124x; 1.0084x over previous
#include <cuda_runtime.h>
#include <cuda_fp16.h>
#include <stdint.h>

#define B_   16
#define LK_  2048
#define LQ_  256
#define DIM_ 512
#define H_   8
#define DK_  64
#define M_   (B_ * LQ_)     // 4096

// q scale folded with log2(e): S lands in log2 domain
#define QSCALE (0.00552427172801990775f * 1.44269504088896341f)

// ---------------- helpers ----------------
__device__ __forceinline__ uint32_t pack_h2(float x, float y) {
    __half2 h = __float22half2_rn(make_float2(x, y));
    return *(uint32_t*)&h;
}
__device__ __forceinline__ void pack_split_h(float x, float y,
                                             uint32_t& hi, uint32_t& lo) {
    __half2 h = __float22half2_rn(make_float2(x, y));
    float2 hf = __half22float2(h);
    __half2 l = __float22half2_rn(make_float2(x - hf.x, y - hf.y));
    hi = *(uint32_t*)&h;
    lo = *(uint32_t*)&l;
}
__device__ __forceinline__ uint32_t ex2h2(uint32_t x) {
    uint32_t r; asm("ex2.approx.f16x2 %0, %1;" : "=r"(r) : "r"(x)); return r;
}
__device__ __forceinline__ void ldsm4(uint32_t* r, uint32_t addr) {
    asm volatile("ldmatrix.sync.aligned.m8n8.x4.shared.b16 {%0,%1,%2,%3}, [%4];"
        : "=r"(r[0]), "=r"(r[1]), "=r"(r[2]), "=r"(r[3]) : "r"(addr));
}
__device__ __forceinline__ void ldsm4t(uint32_t* r, uint32_t addr) {
    asm volatile("ldmatrix.sync.aligned.m8n8.x4.trans.shared.b16 {%0,%1,%2,%3}, [%4];"
        : "=r"(r[0]), "=r"(r[1]), "=r"(r[2]), "=r"(r[3]) : "r"(addr));
}
__device__ __forceinline__ void mma16816(float* c, const uint32_t* a,
                                         uint32_t b0, uint32_t b1) {
    asm volatile("mma.sync.aligned.m16n8k16.row.col.f32.f16.f16.f32 "
        "{%0,%1,%2,%3}, {%4,%5,%6,%7}, {%8,%9}, {%0,%1,%2,%3};"
        : "+f"(c[0]), "+f"(c[1]), "+f"(c[2]), "+f"(c[3])
        : "r"(a[0]), "r"(a[1]), "r"(a[2]), "r"(a[3]), "r"(b0), "r"(b1));
}
__device__ __forceinline__ void mma16816h(uint32_t* c, const uint32_t* a,
                                          uint32_t b0, uint32_t b1) {
    asm volatile("mma.sync.aligned.m16n8k16.row.col.f16.f16.f16.f16 "
        "{%0,%1}, {%2,%3,%4,%5}, {%6,%7}, {%0,%1};"
        : "+r"(c[0]), "+r"(c[1])
        : "r"(a[0]), "r"(a[1]), "r"(a[2]), "r"(a[3]), "r"(b0), "r"(b1));
}
__device__ __forceinline__ void cp16(uint32_t dst, const void* src) {
    asm volatile("cp.async.cg.shared.global [%0], [%1], 16;" :: "r"(dst), "l"(src));
}

// ---------------- scratch (__device__ globals) ----------------
__device__ __half g_gh [M_ * DIM_];
__device__ __half g_xh [M_ * DIM_];
__device__ __half g_wqh[DIM_ * DIM_];
__device__ __half g_woh[DIM_ * DIM_], g_wol[DIM_ * DIM_];

// ---------------------------------------------------------------------------
// Prep (vectorized, MLP=4): 16 floats per thread via 4 independent float4
// loads. G -> fp16; Wq -> fp16; Wo -> fp16 hi/lo.
// ---------------------------------------------------------------------------
#define NG16 (M_ * DIM_ / 16)      // 131072
#define NW16 (DIM_ * DIM_ / 16)    // 16384

__global__ void prep_kernel(const float* __restrict__ G,
                            const float* __restrict__ Wq,
                            const float* __restrict__ Wo) {
    int i = blockIdx.x * blockDim.x + threadIdx.x;
    if (i < NG16) {
        const float4* src = (const float4*)G + (size_t)i * 4;
        float4 v0 = src[0], v1 = src[1], v2 = src[2], v3 = src[3];
        uint4* dst = (uint4*)g_gh + (size_t)i * 2;
        dst[0] = make_uint4(pack_h2(v0.x, v0.y), pack_h2(v0.z, v0.w),
                            pack_h2(v1.x, v1.y), pack_h2(v1.z, v1.w));
        dst[1] = make_uint4(pack_h2(v2.x, v2.y), pack_h2(v2.z, v2.w),
                            pack_h2(v3.x, v3.y), pack_h2(v3.z, v3.w));
    } else if (i < NG16 + NW16) {
        int j = i - NG16;
        const float4* src = (const float4*)Wq + (size_t)j * 4;
        float4 v0 = src[0], v1 = src[1], v2 = src[2], v3 = src[3];
        uint4* dst = (uint4*)g_wqh + (size_t)j * 2;
        dst[0] = make_uint4(pack_h2(v0.x, v0.y), pack_h2(v0.z, v0.w),
                            pack_h2(v1.x, v1.y), pack_h2(v1.z, v1.w));
        dst[1] = make_uint4(pack_h2(v2.x, v2.y), pack_h2(v2.z, v2.w),
                            pack_h2(v3.x, v3.y), pack_h2(v3.z, v3.w));
    } else if (i < NG16 + 2 * NW16) {
        int j = i - NG16 - NW16;
        const float4* src = (const float4*)Wo + (size_t)j * 4;
        float4 v[4] = {src[0], src[1], src[2], src[3]};
        uint32_t hi[8], lo[8];
        #pragma unroll
        for (int k = 0; k < 4; ++k) {
            pack_split_h(v[k].x, v[k].y, hi[2 * k],     lo[2 * k]);
            pack_split_h(v[k].z, v[k].w, hi[2 * k + 1], lo[2 * k + 1]);
        }
        uint4* dh = (uint4*)g_woh + (size_t)j * 2;
        uint4* dl = (uint4*)g_wol + (size_t)j * 2;
        dh[0] = make_uint4(hi[0], hi[1], hi[2], hi[3]);
        dh[1] = make_uint4(hi[4], hi[5], hi[6], hi[7]);
        dl[0] = make_uint4(lo[0], lo[1], lo[2], lo[3]);
        dl[1] = make_uint4(lo[4], lo[5], lo[6], lo[7]);
    }
}

// ---------------------------------------------------------------------------
// GEMM 2-term hi/lo (output projection) — exact R11 structure.
// ---------------------------------------------------------------------------
#define G2_STAGE 16384
#define G2_WH    8192
#define G2_WL    12288
#define GEMM2_SMEM (3 * G2_STAGE)   // 48 KB

__global__ __launch_bounds__(256, 2)
void gemm2_kernel(const __half* __restrict__ Ah,
                  const __half* __restrict__ Wh,
                  const __half* __restrict__ Wl,
                  const float* __restrict__ bias,
                  float* __restrict__ C) {
    extern __shared__ char sm[];
    const uint32_t sb = (uint32_t)__cvta_generic_to_shared(sm);
    const int tid = threadIdx.x, wid = tid >> 5, lane = tid & 31;
    const int g = lane >> 2, t = lane & 3;
    const int wm = wid & 3, wn = wid >> 2;
    const int n0 = blockIdx.x * 64, m0 = blockIdx.y * 128;

    auto issue = [&](int kb, int st) {
        uint32_t base = sb + (uint32_t)st * G2_STAGE;
        #pragma unroll
        for (int i = 0; i < 2; ++i) {
            int lin = tid + i * 256;
            int row = lin >> 2, c = lin & 3;
            uint32_t off = (uint32_t)(row * 64 + c * 16);
            off ^= (off >> 3) & 0x30;
            cp16(base + off, Ah + (size_t)(m0 + row) * DIM_ + kb * 32 + c * 8);
        }
        {
            int row = tid >> 3, c = tid & 7;
            uint32_t off = (uint32_t)(row * 128 + c * 16);
            off ^= (off >> 3) & 0x70;
            size_t src = (size_t)(kb * 32 + row) * DIM_ + n0 + c * 8;
            cp16(base + G2_WH + off, Wh + src);
            cp16(base + G2_WL + off, Wl + src);
        }
        asm volatile("cp.async.commit_group;");
    };

    float acc[2][4][4];
    #pragma unroll
    for (int i = 0; i < 2; ++i)
        #pragma unroll
        for (int j = 0; j < 4; ++j)
            #pragma unroll
            for (int r = 0; r < 4; ++r) acc[i][j][r] = 0.f;

    const uint32_t aColByte = (uint32_t)((lane >> 4) * 16);
    const uint32_t xr    = (uint32_t)(lane & 7) << 4;
    const uint32_t wRowB = (uint32_t)((lane & 15) * 128);
    const uint32_t wD    = (uint32_t)((lane >> 4) * 16);
    const uint32_t wCol  = (uint32_t)(wn * 64);

    issue(0, 0);
    issue(1, 1);

    for (int kb = 0; kb < 16; ++kb) {
        asm volatile("cp.async.wait_group 1;");
        __syncthreads();
        if (kb + 2 < 16) issue(kb + 2, (kb + 2) % 3);

        uint32_t base = sb + (uint32_t)(kb % 3) * G2_STAGE;
        #pragma unroll
        for (int s = 0; s < 2; ++s) {
            uint32_t af[2][4];
            #pragma unroll
            for (int mf = 0; mf < 2; ++mf) {
                uint32_t off = (uint32_t)((wm * 32 + mf * 16 + (lane & 15)) * 64)
                             + (uint32_t)(s * 32) + aColByte;
                off ^= (off >> 3) & 0x30;
                ldsm4(af[mf], base + off);
            }
            #pragma unroll
            for (int nq = 0; nq < 2; ++nq) {
                uint32_t wo = (uint32_t)(s * 16 * 128) + wRowB +
                              ((wCol + (uint32_t)(nq * 32) + wD) ^ xr);
                uint32_t bh[4], bl[4];
                ldsm4t(bh, base + G2_WH + wo);
                ldsm4t(bl, base + G2_WL + wo);
                #pragma unroll
                for (int mf = 0; mf < 2; ++mf) {
                    mma16816(acc[mf][2 * nq],     af[mf], bh[0], bh[1]);
                    mma16816(acc[mf][2 * nq + 1], af[mf], bh[2], bh[3]);
                    mma16816(acc[mf][2 * nq],     af[mf], bl[0], bl[1]);
                    mma16816(acc[mf][2 * nq + 1], af[mf], bl[2], bl[3]);
                }
            }
        }
        __syncthreads();
    }

    #pragma unroll
    for (int mf = 0; mf < 2; ++mf) {
        int r0 = m0 + wm * 32 + mf * 16 + g;
        #pragma unroll
        for (int nj = 0; nj < 4; ++nj) {
            int c = n0 + wn * 32 + nj * 8 + 2 * t;
            float2 bv = *(const float2*)&bias[c];
            *(float2*)&C[(size_t)r0 * DIM_ + c] =
                make_float2(acc[mf][nj][0] + bv.x, acc[mf][nj][1] + bv.y);
            *(float2*)&C[(size_t)(r0 + 8) * DIM_ + c] =
                make_float2(acc[mf][nj][2] + bv.x, acc[mf][nj][3] + bv.y);
        }
    }
}

// ---------------------------------------------------------------------------
// Fused Q-projection + FA2 attention — exact R15 structure.
// ---------------------------------------------------------------------------
#define QP_STAGE 12288
#define QP_W     8192
#define ONES_H2  0x3C003C00u

__global__ __launch_bounds__(256, 2)
void attn_fused_kernel(const float* __restrict__ Lp,
                       const __half* __restrict__ Gh,
                       const __half* __restrict__ Wqh,
                       const float* __restrict__ bq,
                       __half* __restrict__ Xh) {
    __shared__ __align__(128) char smem_raw[3 * QP_STAGE];   // 36 KB

    const int tid  = threadIdx.x;
    const int wid  = tid >> 5;
    const int lane = tid & 31;
    const int g = lane >> 2, t = lane & 3;
    const int qb = blockIdx.x, h = blockIdx.y, b = blockIdx.z;

    const uint32_t sb = (uint32_t)__cvta_generic_to_shared(smem_raw);

    const uint32_t xr    = (uint32_t)(lane & 7) << 4;
    const uint32_t wD    = (uint32_t)((lane >> 4) * 16);
    const uint32_t wRowB = (uint32_t)((lane & 15) * 128);
    const uint32_t aColByte = (uint32_t)((lane >> 4) * 16);

    // ======================= Q-projection prologue =======================
    uint32_t qa[4][4];
    {
        const int m0 = (b * 2 + qb) * 128;
        const int n0 = h * DK_;

        auto issueQ = [&](int kb, int st) {
            uint32_t base = sb + (uint32_t)st * QP_STAGE;
            #pragma unroll
            for (int i = 0; i < 2; ++i) {
                int lin = tid + i * 256;
                int row = lin >> 2, c = lin & 3;
                uint32_t off = (uint32_t)(row * 64 + c * 16);
                off ^= (off >> 3) & 0x30;
                cp16(base + off, Gh + (size_t)(m0 + row) * DIM_ + kb * 32 + c * 8);
            }
            {
                int row = tid >> 3, c = tid & 7;
                uint32_t off = (uint32_t)(row * 128 + c * 16);
                off ^= (off >> 3) & 0x70;
                cp16(base + QP_W + off,
                     Wqh + (size_t)(kb * 32 + row) * DIM_ + n0 + c * 8);
            }
            asm volatile("cp.async.commit_group;");
        };

        float acc[8][4];
        #pragma unroll
        for (int j = 0; j < 8; ++j) {
            acc[j][0] = 0.f; acc[j][1] = 0.f; acc[j][2] = 0.f; acc[j][3] = 0.f;
        }

        issueQ(0, 0);
        issueQ(1, 1);

        for (int kb = 0; kb < 16; ++kb) {
            asm volatile("cp.async.wait_group 1;");
            __syncthreads();
            if (kb + 2 < 16) issueQ(kb + 2, (kb + 2) % 3);

            uint32_t base = sb + (uint32_t)(kb % 3) * QP_STAGE;
            #pragma unroll
            for (int s = 0; s < 2; ++s) {
                uint32_t af[4];
                {
                    uint32_t off = (uint32_t)((wid * 16 + (lane & 15)) * 64)
                                 + (uint32_t)(s * 32) + aColByte;
                    off ^= (off >> 3) & 0x30;
                    ldsm4(af, base + off);
                }
                #pragma unroll
                for (int nq = 0; nq < 4; ++nq) {
                    uint32_t wo = (uint32_t)(s * 16 * 128) + wRowB +
                                  (((uint32_t)(nq * 32) + wD) ^ xr);
                    uint32_t bh[4];
                    ldsm4t(bh, base + QP_W + wo);
                    mma16816(acc[2 * nq],     af, bh[0], bh[1]);
                    mma16816(acc[2 * nq + 1], af, bh[2], bh[3]);
                }
            }
            __syncthreads();
        }

        #pragma unroll
        for (int s = 0; s < 4; ++s) {
            float2 b0 = *(const float2*)&bq[h * DK_ + (2 * s) * 8 + 2 * t];
            float2 b1 = *(const float2*)&bq[h * DK_ + (2 * s + 1) * 8 + 2 * t];
            qa[s][0] = pack_h2((acc[2 * s][0] + b0.x) * QSCALE,
                               (acc[2 * s][1] + b0.y) * QSCALE);
            qa[s][1] = pack_h2((acc[2 * s][2] + b0.x) * QSCALE,
                               (acc[2 * s][3] + b0.y) * QSCALE);
            qa[s][2] = pack_h2((acc[2 * s + 1][0] + b1.x) * QSCALE,
                               (acc[2 * s + 1][1] + b1.y) * QSCALE);
            qa[s][3] = pack_h2((acc[2 * s + 1][2] + b1.x) * QSCALE,
                               (acc[2 * s + 1][3] + b1.y) * QSCALE);
        }
    }
    __syncthreads();

    // ======================= attention mainloop =====================
    const int lr0 = tid >> 4;
    const int ld4 = (tid & 15) * 4;
    const float* lbase = Lp + (size_t)b * LK_ * DIM_ + h * DK_;

    float4 pf[4];
    #pragma unroll
    for (int it = 0; it < 4; ++it)
        pf[it] = *(const float4*)&lbase[(size_t)(lr0 + it * 16) * DIM_ + ld4];

    auto store_half = [&](int buf) {
        #pragma unroll
        for (int it = 0; it < 4; ++it) {
            int r = lr0 + it * 16;
            uint32_t off = (uint32_t)(r * 128 + ld4 * 2);
            off = off ^ ((off >> 3) & 0x70);
            *(uint2*)(smem_raw + buf * 8192 + off) =
                make_uint2(pack_h2(pf[it].x, pf[it].y), pack_h2(pf[it].z, pf[it].w));
        }
    };
    auto load_half = [&](int j) {
        #pragma unroll
        for (int it = 0; it < 4; ++it)
            pf[it] = *(const float4*)
                &lbase[(size_t)(j * 64 + lr0 + it * 16) * DIM_ + ld4];
    };

    float oacc[8][4];
    #pragma unroll
    for (int i = 0; i < 8; ++i)
        #pragma unroll
        for (int j = 0; j < 4; ++j) oacc[i][j] = 0.f;
    float lfrag[4] = {0.f, 0.f, 0.f, 0.f};

    const uint32_t sRow  = (uint32_t)(lane & 7) * 128;
    const uint32_t sOff0 = sRow + ((((uint32_t)(lane >> 3)) * 16 +  0) ^ xr);
    const uint32_t sOff1 = sRow + ((((uint32_t)(lane >> 3)) * 16 + 64) ^ xr);
    const uint32_t vRow  = (uint32_t)(lane & 15) * 128;

    store_half(0);
    load_half(1);
    __syncthreads();

    for (int i = 0; i < 32; ++i) {
        const uint32_t bo = (uint32_t)((i & 1) * 8192);

        uint32_t sacc[8][2];
        #pragma unroll
        for (int nf = 0; nf < 8; ++nf) { sacc[nf][0] = 0u; sacc[nf][1] = 0u; }
        #pragma unroll
        for (int np = 0; np < 4; ++np) {
            uint32_t bA[8], bB[8];
            uint32_t base0 = sb + bo + (uint32_t)(2 * np * 1024);
            ldsm4(bA + 0, base0 + sOff0);
            ldsm4(bA + 4, base0 + sOff1);
            ldsm4(bB + 0, base0 + 1024 + sOff0);
            ldsm4(bB + 4, base0 + 1024 + sOff1);
            #pragma unroll
            for (int s = 0; s < 4; ++s) {
                mma16816h(sacc[2 * np],     qa[s], bA[2 * s], bA[2 * s + 1]);
                mma16816h(sacc[2 * np + 1], qa[s], bB[2 * s], bB[2 * s + 1]);
            }
        }

        #pragma unroll
        for (int u = 0; u < 4; ++u) {
            uint32_t pa[4];
            pa[0] = ex2h2(sacc[2 * u][0]);
            pa[1] = ex2h2(sacc[2 * u][1]);
            pa[2] = ex2h2(sacc[2 * u + 1][0]);
            pa[3] = ex2h2(sacc[2 * u + 1][1]);
            mma16816(lfrag, pa, ONES_H2, ONES_H2);
            #pragma unroll
            for (int dfp = 0; dfp < 4; ++dfp) {
                uint32_t voff = bo + vRow + (uint32_t)(u * 2048)
                              + (((uint32_t)(dfp * 32) + wD) ^ xr);
                uint32_t vh[4];
                ldsm4t(vh, sb + voff);
                mma16816(oacc[2 * dfp],     pa, vh[0], vh[1]);
                mma16816(oacc[2 * dfp + 1], pa, vh[2], vh[3]);
            }
        }

        if (i < 31) {
            store_half((i + 1) & 1);
            if (i < 30) load_half(i + 2);
            __syncthreads();
        }
    }

    float inv0 = 1.f / lfrag[0], inv1 = 1.f / lfrag[2];

    size_t r0 = ((size_t)b * LQ_ + (size_t)qb * 128 + wid * 16 + g) * DIM_ + h * DK_;
    size_t r1 = r0 + 8 * DIM_;
    #pragma unroll
    for (int df = 0; df < 8; ++df) {
        int c = df * 8 + 2 * t;
        *(uint32_t*)((char*)Xh + (r0 + c) * 2) =
            pack_h2(oacc[df][0] * inv0, oacc[df][1] * inv0);
        *(uint32_t*)((char*)Xh + (r1 + c) * 2) =
            pack_h2(oacc[df][2] * inv1, oacc[df][3] * inv1);
    }
}

// ---------------------------------------------------------------------------
extern "C" void kernel_launch(void* const* d_in, const int* in_sizes, int n_in,
                              void* d_out, int out_size) {
    const float* L  = (const float*)d_in[0];
    const float* G  = (const float*)d_in[1];
    const float* Wq = (const float*)d_in[2];
    const float* bq = (const float*)d_in[3];
    const float* Wo = (const float*)d_in[4];
    const float* bo = (const float*)d_in[5];
    float* out = (float*)d_out;

    __half *gh, *xh, *wqh, *woh, *wol;
    cudaGetSymbolAddress((void**)&gh,  g_gh);
    cudaGetSymbolAddress((void**)&xh,  g_xh);
    cudaGetSymbolAddress((void**)&wqh, g_wqh);
    cudaGetSymbolAddress((void**)&woh, g_woh);
    cudaGetSymbolAddress((void**)&wol, g_wol);

    cudaFuncSetAttribute(gemm2_kernel,
                         cudaFuncAttributeMaxDynamicSharedMemorySize, GEMM2_SMEM);

    dim3 gGemm(DIM_ / 64, M_ / 128);            // (8, 32) = 256 CTAs
    dim3 gAttn(LQ_ / 128, H_, B_);              // (2, 8, 16) = 256 CTAs
    int prepBlocks = (NG16 + 2 * NW16 + 255) / 256;   // 640 CTAs

    prep_kernel<<<prepBlocks, 256>>>(G, Wq, Wo);
    attn_fused_kernel<<<gAttn, 256>>>(L, gh, wqh, bq, xh);
    gemm2_kernel<<<gGemm, 256, GEMM2_SMEM>>>(xh, woh, wol, bo, out);
}